// round 5
// baseline (speedup 1.0000x reference)
#include <cuda_runtime.h>
#include <math.h>

// FNetBlock: B=4, L=512, D=64, LAG=32  (2048 rows)
// out[row,d] = b0 + c[row,d] * (c>0 ? A_pos[row] : A_neg[row])
//   c[row,d] = sum_e x[row,e] cos(2*pi*d*e/64)
//   m[row,f] = sum_j mask[row,j] cos(2*pi*f*j/512), f=0..256
//   s = sort(m);  A_pos = sum_k W[k] s[k]      + W[32+k] s[225+k]
//                 A_neg = sum_k W[k] s[256-k]  + W[32+k] s[31-k]
// Two radix-2 folds -> 64-term DFT. Each DFT thread computes f AND f+64
// (same parity => same data stream): 1 LDS.128 per 2 a's, 8 FFMA per a.
// Warps 2-3 do the x-transform + m[128] concurrently. Selection of
// bottom-32/top-32 via register bitonic sort + merges (unchanged).

__global__ __launch_bounds__(256) void fnet_kernel(
    const float* __restrict__ x,     // [2048, 64]
    const float* __restrict__ mask,  // [2048, 512]
    const float* __restrict__ W,     // [64]
    const float* __restrict__ bvec,  // [1]
    float* __restrict__ out)         // [2048, 64]
{
    __shared__ float  sb[2][512];        // mask rows (u)
    __shared__ float2 foldP[2][2][66];   // [row][parity][a] = (we, wo); pad 2
    __shared__ float  marr[2][260];      // m values per row (257 used)
    __shared__ float  xs[2][64];
    __shared__ float  slow[2][4][32];
    __shared__ float  shigh[2][4][32];
    __shared__ float  mbuf[2][4][32];
    __shared__ float  sm128[2];
    __shared__ float  sPP[2][2], sPN[2][2];
    __shared__ float  s8[8];             // cos(pi*k/4)

    const int tid  = threadIdx.x;
    const int lane = tid & 31;
    const int r    = tid >> 7;           // row within block
    const int tl   = tid & 127;
    const int wr   = (tid >> 5) & 3;     // warp within row
    const int row0 = blockIdx.x * 2;

    if (tid < 8) {
        const float rt = 0.70710678118654752f;
        float v = (tid==0)?1.f:(tid==1)?rt:(tid==2)?0.f:(tid==3)?-rt:
                  (tid==4)?-1.f:(tid==5)?-rt:(tid==6)?0.f:rt;
        s8[tid] = v;
    }
    // coalesced vectorized loads
    {
        const float4* m4 = (const float4*)(mask + row0 * 512);
        ((float4*)&sb[0][0])[tid] = m4[tid];
    }
    if (tid < 32) {
        const float4* x4 = (const float4*)(x + row0 * 64);
        ((float4*)&xs[0][0])[tid] = x4[tid];
    }
    __syncthreads();

    // ---- double fold: we_p[a], wo_p[a], a=0..63, parity p; s=(-1)^p ----
    {
        const int rr = tid >> 7;
        const int pp = (tid >> 6) & 1;
        const int a  = tid & 63;
        const float s = pp ? -1.0f : 1.0f;
        const float* u = sb[rr];
        float we, wo;
        if (a == 0) {
            we = fmaf(s, u[256], u[0]);
            wo = (u[1] + u[511]) + s * (u[255] + u[257]);
        } else {
            we = (u[2*a] + u[512-2*a]) + s * (u[256-2*a] + u[256+2*a]);
            wo = (u[2*a+1] + u[511-2*a]) + s * (u[255-2*a] + u[257+2*a]);
        }
        foldP[rr][pp][a] = make_float2(we, wo);
    }
    __syncthreads();

    float cval = 0.f;   // x-transform result (warps 2,3)

    if (tl < 64) {
        // ================= DFT: frequencies f and g=f+64 =================
        const int f = tl;                 // 0..63
        const int p = f & 1;
        float cphi, sphi, cpsi, spsi;
        sincospif((float)f * (1.0f/128.0f), &sphi, &cphi);  // phi = 2*pi*f/256
        sincospif((float)f * (1.0f/256.0f), &spsi, &cpsi);  // psi = pi*f/256
        // g-stream angles: phi_g = phi + pi/2, psi_g = psi + pi/4
        const float R = 0.70710678118654752f;
        const float cphg = -sphi, sphg = cphi;
        const float cpsg = (cpsi - spsi) * R;
        const float spsg = (cpsi + spsi) * R;

        const float t1 = 2.0f * cphi;
        const float t2 = 2.0f * cphg;

        float cc1 = 1.f, cp1 = cphi;
        float wc1 = cpsi, wp1 = fmaf(cpsi, cphi, spsi * sphi);
        float cc2 = 1.f, cp2 = cphg;
        float wc2 = cpsg, wp2 = fmaf(cpsg, cphg, spsg * sphg);
        float E1 = 0.f, O1 = 0.f, E2 = 0.f, O2 = 0.f;

        const float4* wq = (const float4*)&foldP[r][p][0];  // (we,wo) pairs
        #pragma unroll
        for (int a2 = 0; a2 < 16; a2++) {
            float4 q = wq[a2];
            E1 = fmaf(q.x, cc1, E1);  O1 = fmaf(q.y, wc1, O1);
            E2 = fmaf(q.x, cc2, E2);  O2 = fmaf(q.y, wc2, O2);
            float n1 = fmaf(t1, cc1, -cp1); cp1 = cc1; cc1 = n1;
            float m1 = fmaf(t1, wc1, -wp1); wp1 = wc1; wc1 = m1;
            float n2 = fmaf(t2, cc2, -cp2); cp2 = cc2; cc2 = n2;
            float m2 = fmaf(t2, wc2, -wp2); wp2 = wc2; wc2 = m2;
            E1 = fmaf(q.z, cc1, E1);  O1 = fmaf(q.w, wc1, O1);
            E2 = fmaf(q.z, cc2, E2);  O2 = fmaf(q.w, wc2, O2);
            n1 = fmaf(t1, cc1, -cp1); cp1 = cc1; cc1 = n1;
            m1 = fmaf(t1, wc1, -wp1); wp1 = wc1; wc1 = m1;
            n2 = fmaf(t2, cc2, -cp2); cp2 = cc2; cc2 = n2;
            m2 = fmaf(t2, wc2, -wp2); wp2 = wc2; wc2 = m2;
        }
        {   // exact reseed at a=32: cos/sin(32*phi) = cos/sin(pi*f/4); same for g
            int k8 = f & 7;
            float c32 = s8[k8];
            float s32 = s8[(k8 + 6) & 7];
            cc1 = c32;
            cp1 = fmaf(c32, cphi, s32 * sphi);
            float sw1 = fmaf(s32, cpsi, c32 * spsi);
            wc1 = fmaf(c32, cpsi, -(s32 * spsi));
            wp1 = fmaf(wc1, cphi, sw1 * sphi);
            cc2 = c32;
            cp2 = fmaf(c32, cphg, s32 * sphg);
            float sw2 = fmaf(s32, cpsg, c32 * spsg);
            wc2 = fmaf(c32, cpsg, -(s32 * spsg));
            wp2 = fmaf(wc2, cphg, sw2 * sphg);
        }
        #pragma unroll
        for (int a2 = 16; a2 < 32; a2++) {
            float4 q = wq[a2];
            E1 = fmaf(q.x, cc1, E1);  O1 = fmaf(q.y, wc1, O1);
            E2 = fmaf(q.x, cc2, E2);  O2 = fmaf(q.y, wc2, O2);
            float n1 = fmaf(t1, cc1, -cp1); cp1 = cc1; cc1 = n1;
            float m1 = fmaf(t1, wc1, -wp1); wp1 = wc1; wc1 = m1;
            float n2 = fmaf(t2, cc2, -cp2); cp2 = cc2; cc2 = n2;
            float m2 = fmaf(t2, wc2, -wp2); wp2 = wc2; wc2 = m2;
            E1 = fmaf(q.z, cc1, E1);  O1 = fmaf(q.w, wc1, O1);
            E2 = fmaf(q.z, cc2, E2);  O2 = fmaf(q.w, wc2, O2);
            n1 = fmaf(t1, cc1, -cp1); cp1 = cc1; cc1 = n1;
            m1 = fmaf(t1, wc1, -wp1); wp1 = wc1; wc1 = m1;
            n2 = fmaf(t2, cc2, -cp2); cp2 = cc2; cc2 = n2;
            m2 = fmaf(t2, wc2, -wp2); wp2 = wc2; wc2 = m2;
        }
        if (p == 0) {   // tail: v_e[64]*cos(pi*f/2); same sign for g=f+64
            float t64 = sb[r][128] + sb[r][384];
            float tt = (f & 2) ? -t64 : t64;
            E1 += tt; E2 += tt;
        }
        marr[r][f]        = E1 + O1;   // m[f]
        marr[r][256 - f]  = E1 - O1;   // m[256-f]
        marr[r][f + 64]   = E2 + O2;   // m[f+64]
        marr[r][192 - f]  = E2 - O2;   // m[192-f]
    } else {
        // ============ x-transform (d = tl-64) + m[128] (warp 2) ============
        int d = tl - 64;
        float cph, sph;
        sincospif((float)d * (1.0f/32.0f), &sph, &cph);  // 2*pi*d/64
        float td = 2.f * cph;
        float c0 = 1.f, c1m = cph;
        const float* xr = xs[r];
        #pragma unroll
        for (int e = 0; e < 32; e++) {
            cval = fmaf(xr[e], c0, cval);
            float cn = fmaf(td, c0, -c1m); c1m = c0; c0 = cn;
        }
        float sgn = (d & 1) ? -1.f : 1.f;                // cos(pi*d)
        c0 = sgn; c1m = sgn * cph;
        #pragma unroll
        for (int e = 32; e < 64; e++) {
            cval = fmaf(xr[e], c0, cval);
            float cn = fmaf(td, c0, -c1m); c1m = c0; c0 = cn;
        }
        if (wr == 2) {   // m[128] = sum_b u[4b] - u[4b+2]
            const float* u = sb[r];
            float s = 0.f;
            #pragma unroll
            for (int q = 0; q < 4; q++) {
                int b = lane + q * 32;
                s += u[4*b] - u[4*b+2];
            }
            #pragma unroll
            for (int o = 16; o; o >>= 1) s += __shfl_xor_sync(0xffffffffu, s, o);
            if (lane == 0) sm128[r] = s;
        }
    }
    __syncthreads();

    // ---- load (m[tl], m[256-tl]); tl=0..127 excludes index 128 ----
    float v0 = marr[r][tl];
    float v1 = marr[r][256 - tl];

    // ---- warp bitonic sort of 64 (2 regs/lane), ascending ----
    #pragma unroll
    for (int k = 2; k <= 32; k <<= 1) {
        #pragma unroll
        for (int j = k >> 1; j > 0; j >>= 1) {
            bool up0 = ((lane & k) == 0);
            bool up1 = (((lane + 32) & k) == 0);
            float p0 = __shfl_xor_sync(0xffffffffu, v0, j);
            float p1 = __shfl_xor_sync(0xffffffffu, v1, j);
            bool low = ((lane & j) == 0);
            v0 = (low == up0) ? fminf(v0, p0) : fmaxf(v0, p0);
            v1 = (low == up1) ? fminf(v1, p1) : fmaxf(v1, p1);
        }
    }
    {   // k = 64 stage: j=32 crosses regs, then clean
        float lo = fminf(v0, v1), hi = fmaxf(v0, v1);
        v0 = lo; v1 = hi;
        #pragma unroll
        for (int j = 16; j > 0; j >>= 1) {
            float p0 = __shfl_xor_sync(0xffffffffu, v0, j);
            float p1 = __shfl_xor_sync(0xffffffffu, v1, j);
            bool low = ((lane & j) == 0);
            v0 = low ? fminf(v0, p0) : fmaxf(v0, p0);
            v1 = low ? fminf(v1, p1) : fmaxf(v1, p1);
        }
    }
    slow [r][wr][lane] = v0;   // bottom 32 ascending
    shigh[r][wr][lane] = v1;   // top 32 ascending
    __syncthreads();

    // ---- level-1 merges (keep 32 extremes of 64) ----
    {
        float res;
        if      (wr == 0) res = fminf(slow [r][0][lane], slow [r][1][31-lane]);
        else if (wr == 1) res = fminf(slow [r][2][lane], slow [r][3][31-lane]);
        else if (wr == 2) res = fmaxf(shigh[r][0][lane], shigh[r][1][31-lane]);
        else              res = fmaxf(shigh[r][2][lane], shigh[r][3][31-lane]);
        #pragma unroll
        for (int j = 16; j > 0; j >>= 1) {   // bitonic clean -> ascending
            float pv = __shfl_xor_sync(0xffffffffu, res, j);
            res = ((lane & j) == 0) ? fminf(res, pv) : fmaxf(res, pv);
        }
        mbuf[r][wr][lane] = res;
    }
    __syncthreads();

    // ---- final merges + m128 insert + epilogue dots ----
    if (wr == 0) {
        float lowv = fminf(mbuf[r][0][lane], mbuf[r][1][31-lane]);
        #pragma unroll
        for (int j = 16; j > 0; j >>= 1) {
            float pv = __shfl_xor_sync(0xffffffffu, lowv, j);
            lowv = ((lane & j) == 0) ? fminf(lowv, pv) : fmaxf(lowv, pv);
        }
        float m128 = sm128[r];
        unsigned bal = __ballot_sync(0xffffffffu, lowv < m128);
        int cnt = __popc(bal);
        float sh = __shfl_up_sync(0xffffffffu, lowv, 1);
        if (lane >= cnt) lowv = (lane == cnt) ? m128 : sh;
        float pp = __ldg(&W[lane])      * lowv;
        float pn = __ldg(&W[63 - lane]) * lowv;
        #pragma unroll
        for (int o = 16; o; o >>= 1) {
            pp += __shfl_xor_sync(0xffffffffu, pp, o);
            pn += __shfl_xor_sync(0xffffffffu, pn, o);
        }
        if (lane == 0) { sPP[r][0] = pp; sPN[r][0] = pn; }
    } else if (wr == 1) {
        float highv = fmaxf(mbuf[r][2][lane], mbuf[r][3][31-lane]);
        #pragma unroll
        for (int j = 16; j > 0; j >>= 1) {
            float pv = __shfl_xor_sync(0xffffffffu, highv, j);
            highv = ((lane & j) == 0) ? fminf(highv, pv) : fmaxf(highv, pv);
        }
        float m128 = sm128[r];
        unsigned bal = __ballot_sync(0xffffffffu, highv < m128);
        int cnt = __popc(bal);
        float shd = __shfl_down_sync(0xffffffffu, highv, 1);
        highv = (lane + 1 < cnt) ? shd : ((lane + 1 == cnt) ? m128 : highv);
        float pp = __ldg(&W[32 + lane]) * highv;
        float pn = __ldg(&W[31 - lane]) * highv;
        #pragma unroll
        for (int o = 16; o; o >>= 1) {
            pp += __shfl_xor_sync(0xffffffffu, pp, o);
            pn += __shfl_xor_sync(0xffffffffu, pn, o);
        }
        if (lane == 0) { sPP[r][1] = pp; sPN[r][1] = pn; }
    }
    __syncthreads();

    // ---- output (warps 2,3 of each row; coalesced) ----
    if (wr >= 2) {
        int d = tl - 64;
        float Ap = sPP[r][0] + sPP[r][1];
        float An = sPN[r][0] + sPN[r][1];
        float A = (cval > 0.f) ? Ap : An;
        out[(row0 + r) * 64 + d] = fmaf(cval, A, bvec[0]);
    }
}

extern "C" void kernel_launch(void* const* d_in, const int* in_sizes, int n_in,
                              void* d_out, int out_size) {
    const float* x    = (const float*)d_in[0];
    const float* mask = (const float*)d_in[1];
    const float* W    = (const float*)d_in[2];
    const float* b    = (const float*)d_in[3];
    fnet_kernel<<<1024, 256>>>(x, mask, W, b, (float*)d_out);
}

// round 6
// speedup vs baseline: 1.1604x; 1.1604x over previous
#include <cuda_runtime.h>
#include <math.h>

// FNetBlock: B=4, L=512, D=64, LAG=32  (2048 rows)
// out[row,d] = b0 + c[row,d] * (c>0 ? A_pos[row] : A_neg[row])
//   c[row,d] = sum_e x[row,e] cos(2*pi*d*e/64)
//   m[row,f] = sum_j mask[row,j] cos(2*pi*f*j/512), f=0..256
//   s = sort(m);  A_pos = sum_k W[k] s[k]      + W[32+k] s[225+k]
//                 A_neg = sum_k W[k] s[256-k]  + W[32+k] s[31-k]
// Two radix-2 folds -> 64-term per-thread DFT (parity-dependent arrays).
// Latency-optimized: 4-way split accumulators, 2-step Chebyshev chains
// (depth 32, matches validated reseed interval -> no reseed needed),
// LDS.128 fold reads. Bottom/top-32 via register bitonic selection.

__global__ __launch_bounds__(256) void fnet_kernel(
    const float* __restrict__ x,     // [2048, 64]
    const float* __restrict__ mask,  // [2048, 512]
    const float* __restrict__ W,     // [64]
    const float* __restrict__ bvec,  // [1]
    float* __restrict__ out)         // [2048, 64]
{
    __shared__ float  sb[2][512];                    // mask rows (u)
    __shared__ __align__(16) float2 foldP[2][2][68]; // [row][parity][a]=(we,wo)
    __shared__ float  xs[2][64];
    __shared__ float  slow[2][4][32];
    __shared__ float  shigh[2][4][32];
    __shared__ float  mbuf[2][4][32];
    __shared__ float  sm128[2];
    __shared__ float  sPP[2][2], sPN[2][2];

    const int tid  = threadIdx.x;
    const int lane = tid & 31;
    const int r    = tid >> 7;          // row within block
    const int tl   = tid & 127;
    const int wr   = (tid >> 5) & 3;    // warp within row
    const int row0 = blockIdx.x * 2;

    // ---- trig early (independent of smem; hides MUFU behind load wait) ----
    const int f = tl;
    float cphi, sphi, cpsi, spsi;
    sincospif((float)f * (1.0f/128.0f), &sphi, &cphi);  // phi = 2*pi*f/256
    sincospif((float)f * (1.0f/256.0f), &spsi, &cpsi);  // psi = pi*f/256

    // ---- coalesced vectorized loads ----
    {
        const float4* m4 = (const float4*)(mask + row0 * 512);
        ((float4*)&sb[0][0])[tid] = m4[tid];
    }
    if (tid < 32) {
        const float4* x4 = (const float4*)(x + row0 * 64);
        ((float4*)&xs[0][0])[tid] = x4[tid];
    }
    __syncthreads();

    // ---- double fold: we_p[a], wo_p[a], a=0..63, parity p; s=(-1)^p ----
    {
        const int rr = tid >> 7;
        const int pp = (tid >> 6) & 1;
        const int a  = tid & 63;
        const float s = pp ? -1.0f : 1.0f;
        const float* u = sb[rr];
        float we, wo;
        if (a == 0) {
            we = fmaf(s, u[256], u[0]);
            wo = (u[1] + u[511]) + s * (u[255] + u[257]);
        } else {
            we = (u[2*a] + u[512-2*a]) + s * (u[256-2*a] + u[256+2*a]);
            wo = (u[2*a+1] + u[511-2*a]) + s * (u[255-2*a] + u[257+2*a]);
        }
        foldP[rr][pp][a] = make_float2(we, wo);
    }
    __syncthreads();

    // ---- folded DFT: 64 terms, 2-step Chebyshev chains, 4-way accumulators ----
    const int p = f & 1;
    // seeds: c2=cos(2phi), s2=sin(2phi); t2 = 2*cos(2phi)
    const float c2 = fmaf(2.0f*cphi, cphi, -1.0f);
    const float s2 = 2.0f * sphi * cphi;
    const float t2 = 2.0f * c2;
    // even-a cosine chain: cur=cos(0)=1, prev=cos(-2phi)=c2
    float ce = 1.0f,  cpe = c2;
    // odd-a  cosine chain: cur=cos(phi), prev=cos(-phi)=cos(phi)
    float co = cphi,  cpo = cphi;
    // psi-shifted chains: even cur=cos(psi), prev=cos(psi-2phi)
    float we_ = cpsi, wpe = fmaf(cpsi, c2,  spsi * s2);
    // odd cur=cos(psi+phi), prev=cos(psi-phi)
    float wo_ = fmaf(cpsi, cphi, -(spsi * sphi));
    float wpo = fmaf(cpsi, cphi,  (spsi * sphi));

    float E0 = 0.f, E1 = 0.f, E2 = 0.f, E3 = 0.f;
    float O0 = 0.f, O1 = 0.f, O2 = 0.f, O3 = 0.f;
    const float4* wq = (const float4*)&foldP[r][p][0];  // a=2k,2k+1 per load
    #pragma unroll
    for (int k = 0; k < 32; k += 2) {
        float4 qa = wq[k];
        E0 = fmaf(qa.x, ce,  E0);  O0 = fmaf(qa.y, we_, O0);
        E1 = fmaf(qa.z, co,  E1);  O1 = fmaf(qa.w, wo_, O1);
        float n;
        n = fmaf(t2, ce,  -cpe); cpe = ce;  ce  = n;
        n = fmaf(t2, co,  -cpo); cpo = co;  co  = n;
        n = fmaf(t2, we_, -wpe); wpe = we_; we_ = n;
        n = fmaf(t2, wo_, -wpo); wpo = wo_; wo_ = n;
        float4 qb = wq[k + 1];
        E2 = fmaf(qb.x, ce,  E2);  O2 = fmaf(qb.y, we_, O2);
        E3 = fmaf(qb.z, co,  E3);  O3 = fmaf(qb.w, wo_, O3);
        n = fmaf(t2, ce,  -cpe); cpe = ce;  ce  = n;
        n = fmaf(t2, co,  -cpo); cpo = co;  co  = n;
        n = fmaf(t2, we_, -wpe); wpe = we_; we_ = n;
        n = fmaf(t2, wo_, -wpo); wpo = wo_; wo_ = n;
    }
    float E = (E0 + E2) + (E1 + E3);
    float O = (O0 + O2) + (O1 + O3);
    if (p == 0) {                      // tail: v_e[64]*cos(pi*f/2)
        float t64 = sb[r][128] + sb[r][384];
        E += (f & 2) ? -t64 : t64;
    }
    float v0 = E + O;    // m[f]
    float v1 = E - O;    // m[256-f]

    // ---- m[128] = sum_b u[4b] - u[4b+2], by warp 3 of each row ----
    if (wr == 3) {
        const float* u = sb[r];
        float s = 0.f;
        #pragma unroll
        for (int q = 0; q < 4; q++) {
            int b = lane + q * 32;
            s += u[4*b] - u[4*b+2];
        }
        #pragma unroll
        for (int o = 16; o; o >>= 1) s += __shfl_xor_sync(0xffffffffu, s, o);
        if (lane == 0) sm128[r] = s;
    }

    // ---- warp bitonic sort of 64 (2 regs/lane), ascending ----
    #pragma unroll
    for (int k = 2; k <= 32; k <<= 1) {
        #pragma unroll
        for (int j = k >> 1; j > 0; j >>= 1) {
            bool up0 = ((lane & k) == 0);
            bool up1 = (((lane + 32) & k) == 0);
            float p0 = __shfl_xor_sync(0xffffffffu, v0, j);
            float p1 = __shfl_xor_sync(0xffffffffu, v1, j);
            bool low = ((lane & j) == 0);
            v0 = (low == up0) ? fminf(v0, p0) : fmaxf(v0, p0);
            v1 = (low == up1) ? fminf(v1, p1) : fmaxf(v1, p1);
        }
    }
    {   // k = 64 stage: j=32 crosses regs, then clean
        float lo = fminf(v0, v1), hi = fmaxf(v0, v1);
        v0 = lo; v1 = hi;
        #pragma unroll
        for (int j = 16; j > 0; j >>= 1) {
            float p0 = __shfl_xor_sync(0xffffffffu, v0, j);
            float p1 = __shfl_xor_sync(0xffffffffu, v1, j);
            bool low = ((lane & j) == 0);
            v0 = low ? fminf(v0, p0) : fmaxf(v0, p0);
            v1 = low ? fminf(v1, p1) : fmaxf(v1, p1);
        }
    }
    slow [r][wr][lane] = v0;   // bottom 32 ascending
    shigh[r][wr][lane] = v1;   // top 32 ascending
    __syncthreads();

    // ---- level-1 merges (keep 32 extremes of 64) ----
    {
        float res;
        if      (wr == 0) res = fminf(slow [r][0][lane], slow [r][1][31-lane]);
        else if (wr == 1) res = fminf(slow [r][2][lane], slow [r][3][31-lane]);
        else if (wr == 2) res = fmaxf(shigh[r][0][lane], shigh[r][1][31-lane]);
        else              res = fmaxf(shigh[r][2][lane], shigh[r][3][31-lane]);
        #pragma unroll
        for (int j = 16; j > 0; j >>= 1) {   // bitonic clean -> ascending
            float pv = __shfl_xor_sync(0xffffffffu, res, j);
            res = ((lane & j) == 0) ? fminf(res, pv) : fmaxf(res, pv);
        }
        mbuf[r][wr][lane] = res;
    }
    __syncthreads();

    // ---- final merges + m128 insert + epilogue dot  |  x-transform ----
    float cval = 0.f;
    if (wr == 0) {
        float lowv = fminf(mbuf[r][0][lane], mbuf[r][1][31-lane]);
        #pragma unroll
        for (int j = 16; j > 0; j >>= 1) {
            float pv = __shfl_xor_sync(0xffffffffu, lowv, j);
            lowv = ((lane & j) == 0) ? fminf(lowv, pv) : fmaxf(lowv, pv);
        }
        float m128 = sm128[r];
        unsigned bal = __ballot_sync(0xffffffffu, lowv < m128);
        int cnt = __popc(bal);
        float sh = __shfl_up_sync(0xffffffffu, lowv, 1);
        if (lane >= cnt) lowv = (lane == cnt) ? m128 : sh;
        float pp = __ldg(&W[lane])      * lowv;
        float pn = __ldg(&W[63 - lane]) * lowv;
        #pragma unroll
        for (int o = 16; o; o >>= 1) {
            pp += __shfl_xor_sync(0xffffffffu, pp, o);
            pn += __shfl_xor_sync(0xffffffffu, pn, o);
        }
        if (lane == 0) { sPP[r][0] = pp; sPN[r][0] = pn; }
    } else if (wr == 1) {
        float highv = fmaxf(mbuf[r][2][lane], mbuf[r][3][31-lane]);
        #pragma unroll
        for (int j = 16; j > 0; j >>= 1) {
            float pv = __shfl_xor_sync(0xffffffffu, highv, j);
            highv = ((lane & j) == 0) ? fminf(highv, pv) : fmaxf(highv, pv);
        }
        float m128 = sm128[r];
        unsigned bal = __ballot_sync(0xffffffffu, highv < m128);
        int cnt = __popc(bal);
        float shd = __shfl_down_sync(0xffffffffu, highv, 1);
        highv = (lane + 1 < cnt) ? shd : ((lane + 1 == cnt) ? m128 : highv);
        float pp = __ldg(&W[32 + lane]) * highv;
        float pn = __ldg(&W[31 - lane]) * highv;
        #pragma unroll
        for (int o = 16; o; o >>= 1) {
            pp += __shfl_xor_sync(0xffffffffu, pp, o);
            pn += __shfl_xor_sync(0xffffffffu, pn, o);
        }
        if (lane == 0) { sPP[r][1] = pp; sPN[r][1] = pn; }
    } else {
        // 64-point cosine transform of x, 2 split accumulators
        int d = tl - 64;
        float cph, sph;
        sincospif((float)d * (1.0f/32.0f), &sph, &cph);  // 2*pi*d/64
        float td = 2.f * cph;
        float c0 = 1.f, c1m = cph;
        float ca = 0.f, cb = 0.f;
        const float* xr = xs[r];
        #pragma unroll
        for (int e = 0; e < 32; e += 2) {
            ca = fmaf(xr[e],   c0, ca);
            float cn = fmaf(td, c0, -c1m); c1m = c0; c0 = cn;
            cb = fmaf(xr[e+1], c0, cb);
            cn = fmaf(td, c0, -c1m); c1m = c0; c0 = cn;
        }
        float sgn = (d & 1) ? -1.f : 1.f;                // cos(pi*d)
        c0 = sgn; c1m = sgn * cph;
        #pragma unroll
        for (int e = 32; e < 64; e += 2) {
            ca = fmaf(xr[e],   c0, ca);
            float cn = fmaf(td, c0, -c1m); c1m = c0; c0 = cn;
            cb = fmaf(xr[e+1], c0, cb);
            cn = fmaf(td, c0, -c1m); c1m = c0; c0 = cn;
        }
        cval = ca + cb;
    }
    __syncthreads();

    // ---- output (warps 2,3 of each row; coalesced) ----
    if (wr >= 2) {
        int d = tl - 64;
        float Ap = sPP[r][0] + sPP[r][1];
        float An = sPN[r][0] + sPN[r][1];
        float A = (cval > 0.f) ? Ap : An;
        out[(row0 + r) * 64 + d] = fmaf(cval, A, bvec[0]);
    }
}

extern "C" void kernel_launch(void* const* d_in, const int* in_sizes, int n_in,
                              void* d_out, int out_size) {
    const float* x    = (const float*)d_in[0];
    const float* mask = (const float*)d_in[1];
    const float* W    = (const float*)d_in[2];
    const float* b    = (const float*)d_in[3];
    fnet_kernel<<<1024, 256>>>(x, mask, W, b, (float*)d_out);
}

// round 7
// speedup vs baseline: 1.1629x; 1.0022x over previous
#include <cuda_runtime.h>
#include <math.h>

// FNetBlock: B=4, L=512, D=64, LAG=32  (2048 rows)
// out[row,d] = b0 + c[row,d] * (c>0 ? A_pos[row] : A_neg[row])
//   c[row,d] = sum_e x[row,e] cos(2*pi*d*e/64)
//   m[row,f] = sum_j mask[row,j] cos(2*pi*f*j/512), f=0..256
//   s = sort(m);  A_pos = sum_k W[k] s[k]      + W[32+k] s[225+k]
//                 A_neg = sum_k W[k] s[256-k]  + W[32+k] s[31-k]
// One row per 128-thread block (row-scoped barriers, better packing).
// Two radix-2 folds -> 64-term per-thread DFT; 4-way split accumulators,
// 2-step Chebyshev chains (depth 32, validated: no reseed needed).
// Bottom/top-32 via register bitonic selection.

__global__ __launch_bounds__(128) void fnet_kernel(
    const float* __restrict__ x,     // [2048, 64]
    const float* __restrict__ mask,  // [2048, 512]
    const float* __restrict__ W,     // [64]
    const float* __restrict__ bvec,  // [1]
    float* __restrict__ out)         // [2048, 64]
{
    __shared__ float  sb[512];                    // mask row (u)
    __shared__ __align__(16) float2 foldP[2][68]; // [parity][a] = (we, wo)
    __shared__ float  xs[64];
    __shared__ float  slow[4][32];
    __shared__ float  shigh[4][32];
    __shared__ float  mbuf[4][32];
    __shared__ float  sm128;
    __shared__ float  sPP[2], sPN[2];

    const int tid  = threadIdx.x;     // 0..127
    const int lane = tid & 31;
    const int wr   = tid >> 5;        // warp 0..3
    const int row  = blockIdx.x;

    // ---- trig early (independent of smem; hides MUFU behind load wait) ----
    const int f = tid;
    float cphi, sphi, cpsi, spsi;
    sincospif((float)f * (1.0f/128.0f), &sphi, &cphi);  // phi = 2*pi*f/256
    sincospif((float)f * (1.0f/256.0f), &spsi, &cpsi);  // psi = pi*f/256

    // ---- coalesced vectorized loads ----
    {
        const float4* m4 = (const float4*)(mask + row * 512);
        ((float4*)sb)[tid] = m4[tid];
    }
    if (tid < 16) {
        const float4* x4 = (const float4*)(x + row * 64);
        ((float4*)xs)[tid] = x4[tid];
    }
    __syncthreads();

    // ---- double fold: we_p[a], wo_p[a], a=0..63, parity p; s=(-1)^p ----
    {
        const int pp = tid >> 6;
        const int a  = tid & 63;
        const float s = pp ? -1.0f : 1.0f;
        const float* u = sb;
        float we, wo;
        if (a == 0) {
            we = fmaf(s, u[256], u[0]);
            wo = (u[1] + u[511]) + s * (u[255] + u[257]);
        } else {
            we = (u[2*a] + u[512-2*a]) + s * (u[256-2*a] + u[256+2*a]);
            wo = (u[2*a+1] + u[511-2*a]) + s * (u[255-2*a] + u[257+2*a]);
        }
        foldP[pp][a] = make_float2(we, wo);
    }
    __syncthreads();

    // ---- folded DFT: 64 terms, 2-step Chebyshev chains, 4-way accumulators ----
    const int p = f & 1;
    const float c2 = fmaf(2.0f*cphi, cphi, -1.0f);      // cos(2phi)
    const float s2 = 2.0f * sphi * cphi;                // sin(2phi)
    const float t2 = 2.0f * c2;
    float ce = 1.0f,  cpe = c2;                         // even-a cos chain
    float co = cphi,  cpo = cphi;                       // odd-a cos chain
    float we_ = cpsi, wpe = fmaf(cpsi, c2,  spsi * s2); // even psi chain
    float wo_ = fmaf(cpsi, cphi, -(spsi * sphi));       // odd psi chain
    float wpo = fmaf(cpsi, cphi,  (spsi * sphi));

    float E0 = 0.f, E1 = 0.f, E2 = 0.f, E3 = 0.f;
    float O0 = 0.f, O1 = 0.f, O2 = 0.f, O3 = 0.f;
    const float4* wq = (const float4*)&foldP[p][0];     // a=2k,2k+1 per load
    #pragma unroll
    for (int k = 0; k < 32; k += 2) {
        float4 qa = wq[k];
        E0 = fmaf(qa.x, ce,  E0);  O0 = fmaf(qa.y, we_, O0);
        E1 = fmaf(qa.z, co,  E1);  O1 = fmaf(qa.w, wo_, O1);
        float n;
        n = fmaf(t2, ce,  -cpe); cpe = ce;  ce  = n;
        n = fmaf(t2, co,  -cpo); cpo = co;  co  = n;
        n = fmaf(t2, we_, -wpe); wpe = we_; we_ = n;
        n = fmaf(t2, wo_, -wpo); wpo = wo_; wo_ = n;
        float4 qb = wq[k + 1];
        E2 = fmaf(qb.x, ce,  E2);  O2 = fmaf(qb.y, we_, O2);
        E3 = fmaf(qb.z, co,  E3);  O3 = fmaf(qb.w, wo_, O3);
        n = fmaf(t2, ce,  -cpe); cpe = ce;  ce  = n;
        n = fmaf(t2, co,  -cpo); cpo = co;  co  = n;
        n = fmaf(t2, we_, -wpe); wpe = we_; we_ = n;
        n = fmaf(t2, wo_, -wpo); wpo = wo_; wo_ = n;
    }
    float E = (E0 + E2) + (E1 + E3);
    float O = (O0 + O2) + (O1 + O3);
    if (p == 0) {                      // tail: v_e[64]*cos(pi*f/2)
        float t64 = sb[128] + sb[384];
        E += (f & 2) ? -t64 : t64;
    }
    float v0 = E + O;    // m[f]
    float v1 = E - O;    // m[256-f]

    // ---- m[128] = sum_b u[4b] - u[4b+2], by warp 3 ----
    if (wr == 3) {
        float s = 0.f;
        #pragma unroll
        for (int q = 0; q < 4; q++) {
            int b = lane + q * 32;
            s += sb[4*b] - sb[4*b+2];
        }
        #pragma unroll
        for (int o = 16; o; o >>= 1) s += __shfl_xor_sync(0xffffffffu, s, o);
        if (lane == 0) sm128 = s;
    }

    // ---- warp bitonic sort of 64 (2 regs/lane), ascending ----
    #pragma unroll
    for (int k = 2; k <= 32; k <<= 1) {
        #pragma unroll
        for (int j = k >> 1; j > 0; j >>= 1) {
            bool up0 = ((lane & k) == 0);
            bool up1 = (((lane + 32) & k) == 0);
            float p0 = __shfl_xor_sync(0xffffffffu, v0, j);
            float p1 = __shfl_xor_sync(0xffffffffu, v1, j);
            bool low = ((lane & j) == 0);
            v0 = (low == up0) ? fminf(v0, p0) : fmaxf(v0, p0);
            v1 = (low == up1) ? fminf(v1, p1) : fmaxf(v1, p1);
        }
    }
    {   // k = 64 stage: j=32 crosses regs, then clean
        float lo = fminf(v0, v1), hi = fmaxf(v0, v1);
        v0 = lo; v1 = hi;
        #pragma unroll
        for (int j = 16; j > 0; j >>= 1) {
            float p0 = __shfl_xor_sync(0xffffffffu, v0, j);
            float p1 = __shfl_xor_sync(0xffffffffu, v1, j);
            bool low = ((lane & j) == 0);
            v0 = low ? fminf(v0, p0) : fmaxf(v0, p0);
            v1 = low ? fminf(v1, p1) : fmaxf(v1, p1);
        }
    }
    slow [wr][lane] = v0;   // bottom 32 ascending
    shigh[wr][lane] = v1;   // top 32 ascending
    __syncthreads();

    // ---- level-1 merges (keep 32 extremes of 64) ----
    {
        float res;
        if      (wr == 0) res = fminf(slow [0][lane], slow [1][31-lane]);
        else if (wr == 1) res = fminf(slow [2][lane], slow [3][31-lane]);
        else if (wr == 2) res = fmaxf(shigh[0][lane], shigh[1][31-lane]);
        else              res = fmaxf(shigh[2][lane], shigh[3][31-lane]);
        #pragma unroll
        for (int j = 16; j > 0; j >>= 1) {   // bitonic clean -> ascending
            float pv = __shfl_xor_sync(0xffffffffu, res, j);
            res = ((lane & j) == 0) ? fminf(res, pv) : fmaxf(res, pv);
        }
        mbuf[wr][lane] = res;
    }
    __syncthreads();

    // ---- final merges + m128 insert + epilogue dot  |  x-transform ----
    float cval = 0.f;
    if (wr == 0) {
        float lowv = fminf(mbuf[0][lane], mbuf[1][31-lane]);
        #pragma unroll
        for (int j = 16; j > 0; j >>= 1) {
            float pv = __shfl_xor_sync(0xffffffffu, lowv, j);
            lowv = ((lane & j) == 0) ? fminf(lowv, pv) : fmaxf(lowv, pv);
        }
        float m128 = sm128;
        unsigned bal = __ballot_sync(0xffffffffu, lowv < m128);
        int cnt = __popc(bal);
        float sh = __shfl_up_sync(0xffffffffu, lowv, 1);
        if (lane >= cnt) lowv = (lane == cnt) ? m128 : sh;
        float pp = __ldg(&W[lane])      * lowv;
        float pn = __ldg(&W[63 - lane]) * lowv;
        #pragma unroll
        for (int o = 16; o; o >>= 1) {
            pp += __shfl_xor_sync(0xffffffffu, pp, o);
            pn += __shfl_xor_sync(0xffffffffu, pn, o);
        }
        if (lane == 0) { sPP[0] = pp; sPN[0] = pn; }
    } else if (wr == 1) {
        float highv = fmaxf(mbuf[2][lane], mbuf[3][31-lane]);
        #pragma unroll
        for (int j = 16; j > 0; j >>= 1) {
            float pv = __shfl_xor_sync(0xffffffffu, highv, j);
            highv = ((lane & j) == 0) ? fminf(highv, pv) : fmaxf(highv, pv);
        }
        float m128 = sm128;
        unsigned bal = __ballot_sync(0xffffffffu, highv < m128);
        int cnt = __popc(bal);
        float shd = __shfl_down_sync(0xffffffffu, highv, 1);
        highv = (lane + 1 < cnt) ? shd : ((lane + 1 == cnt) ? m128 : highv);
        float pp = __ldg(&W[32 + lane]) * highv;
        float pn = __ldg(&W[31 - lane]) * highv;
        #pragma unroll
        for (int o = 16; o; o >>= 1) {
            pp += __shfl_xor_sync(0xffffffffu, pp, o);
            pn += __shfl_xor_sync(0xffffffffu, pn, o);
        }
        if (lane == 0) { sPP[1] = pp; sPN[1] = pn; }
    } else {
        // 64-point cosine transform of x, 2 split accumulators
        int d = tid - 64;
        float cph, sph;
        sincospif((float)d * (1.0f/32.0f), &sph, &cph);  // 2*pi*d/64
        float td = 2.f * cph;
        float c0 = 1.f, c1m = cph;
        float ca = 0.f, cb = 0.f;
        #pragma unroll
        for (int e = 0; e < 32; e += 2) {
            ca = fmaf(xs[e],   c0, ca);
            float cn = fmaf(td, c0, -c1m); c1m = c0; c0 = cn;
            cb = fmaf(xs[e+1], c0, cb);
            cn = fmaf(td, c0, -c1m); c1m = c0; c0 = cn;
        }
        float sgn = (d & 1) ? -1.f : 1.f;                // cos(pi*d)
        c0 = sgn; c1m = sgn * cph;
        #pragma unroll
        for (int e = 32; e < 64; e += 2) {
            ca = fmaf(xs[e],   c0, ca);
            float cn = fmaf(td, c0, -c1m); c1m = c0; c0 = cn;
            cb = fmaf(xs[e+1], c0, cb);
            cn = fmaf(td, c0, -c1m); c1m = c0; c0 = cn;
        }
        cval = ca + cb;
    }
    __syncthreads();

    // ---- output (warps 2,3; coalesced) ----
    if (wr >= 2) {
        int d = tid - 64;
        float Ap = sPP[0] + sPP[1];
        float An = sPN[0] + sPN[1];
        float A = (cval > 0.f) ? Ap : An;
        out[row * 64 + d] = fmaf(cval, A, bvec[0]);
    }
}

extern "C" void kernel_launch(void* const* d_in, const int* in_sizes, int n_in,
                              void* d_out, int out_size) {
    const float* x    = (const float*)d_in[0];
    const float* mask = (const float*)d_in[1];
    const float* W    = (const float*)d_in[2];
    const float* b    = (const float*)d_in[3];
    fnet_kernel<<<2048, 128>>>(x, mask, W, b, (float*)d_out);
}